// round 6
// baseline (speedup 1.0000x reference)
#include <cuda_runtime.h>
#include <cuda_bf16.h>
#include <math_constants.h>
#include <cstdint>

// Problem shape (fixed by the dataset)
#define BATCH 2
#define SEQ   2048
#define DMODEL 1024
#define NHEAD 16
#define HDIM  64
#define MROWS (BATCH*SEQ)          // 4096

// ---------------------------------------------------------------------------
// Single 64 MiB heap, aliased (known-passing budget):
//   [0, 12M words)   : qkv tf32 [4096][3072] ; later w_projT [1024][1024]
//   [12M, 16M words) : w_qkvT tf32 [3072][1024] ; later att tf32 [4096][1024]
// ---------------------------------------------------------------------------
#define OFF_QKV   0
#define OFF_WPROJ 0
#define OFF_U     (12u * 1024u * 1024u)
__device__ uint32_t g_heap[16u * 1024u * 1024u];

// ---------------------------------------------------------------------------
// helpers
// ---------------------------------------------------------------------------
__device__ __forceinline__ uint32_t f2tf(float x) {
    uint32_t u;
    asm("cvt.rna.tf32.f32 %0, %1;" : "=r"(u) : "f"(x));
    return u;
}
__device__ __forceinline__ uint32_t u2tf(uint32_t xb) {
    return f2tf(__uint_as_float(xb));
}
__device__ __forceinline__ uint32_t smaddr(const void* p) {
    return (uint32_t)__cvta_generic_to_shared(p);
}
__device__ __forceinline__ void ldmx4(uint32_t* r, uint32_t addr) {
    asm volatile("ldmatrix.sync.aligned.m8n8.x4.shared.b16 {%0,%1,%2,%3}, [%4];"
                 : "=r"(r[0]), "=r"(r[1]), "=r"(r[2]), "=r"(r[3]) : "r"(addr));
}
__device__ __forceinline__ void cpasync16(uint32_t dst, const void* src) {
    asm volatile("cp.async.cg.shared.global [%0], [%1], 16;" :: "r"(dst), "l"(src));
}
#define CP_COMMIT() asm volatile("cp.async.commit_group;")
#define CP_WAIT1()  asm volatile("cp.async.wait_group 1;")

// D(16x8) += A(16x8) * B(8x8); fp32 accum.
__device__ __forceinline__ void mma8(float* c, const uint32_t* a, const uint32_t* b) {
    asm volatile(
        "mma.sync.aligned.m16n8k8.row.col.f32.tf32.tf32.f32 "
        "{%0,%1,%2,%3}, {%4,%5,%6,%7}, {%8,%9}, {%0,%1,%2,%3};\n"
        : "+f"(c[0]), "+f"(c[1]), "+f"(c[2]), "+f"(c[3])
        : "r"(a[0]), "r"(a[1]), "r"(a[2]), "r"(a[3]), "r"(b[0]), "r"(b[1]));
}

// ---------------------------------------------------------------------------
// Transpose + convert: W [1024][Ncols] fp32 -> g_heap[dstOff..] [Ncols][1024] tf32
// ---------------------------------------------------------------------------
__global__ __launch_bounds__(256) void transpose_cvt(
    const float* __restrict__ W, unsigned dstOff, int Ncols)
{
    __shared__ uint32_t t[32][33];
    uint32_t* out = g_heap + dstOff;
    const int n0 = blockIdx.x * 32, k0 = blockIdx.y * 32;
    const int tx = threadIdx.x, ty = threadIdx.y;   // 32 x 8
#pragma unroll
    for (int i = 0; i < 32; i += 8)
        t[ty + i][tx] = f2tf(W[(size_t)(k0 + ty + i) * Ncols + n0 + tx]);
    __syncthreads();
#pragma unroll
    for (int i = 0; i < 32; i += 8)
        out[(size_t)(n0 + ty + i) * DMODEL + k0 + tx] = t[tx][ty + i];
}

// ---------------------------------------------------------------------------
// tf32 GEMM, double-buffered cp.async + ldmatrix (unchanged from R5 — proven).
// ---------------------------------------------------------------------------
#define TSTR 20
#define STAGE_BYTES (128 * TSTR * 4)

template<int MODE>
__global__ __launch_bounds__(256) void tgemm(
    const float* __restrict__ Ap, const float* __restrict__ bias,
    float* __restrict__ Cp, int N)
{
    const uint32_t* A = (MODE == 0) ? (const uint32_t*)Ap : g_heap + OFF_U;
    const uint32_t* B = (MODE == 0) ? g_heap + OFF_U : g_heap + OFF_WPROJ;
    uint32_t* Ctf = g_heap + OFF_QKV;
    constexpr int K = DMODEL;

    __shared__ uint32_t As[2][128][TSTR];
    __shared__ uint32_t Bs[2][128][TSTR];

    const int tid  = threadIdx.x;
    const int lane = tid & 31;
    const int wid  = tid >> 5;
    const int g    = lane >> 2;
    const int q    = lane & 3;

    const int bm = blockIdx.y * 128;
    const int bn = blockIdx.x * 128;
    const int wm0 = (wid >> 1) * 32;
    const int wn0 = (wid & 1) * 64;

    const int lrow = tid >> 1;
    const int lk   = (tid & 1) * 8;
    const uint32_t* Asrc = A + (size_t)(bm + lrow) * K + lk;
    const uint32_t* Bsrc = B + (size_t)(bn + lrow) * K + lk;
    const uint32_t dA = smaddr(&As[0][lrow][lk]);
    const uint32_t dB = smaddr(&Bs[0][lrow][lk]);

    const int mat = lane >> 3, r = lane & 7;
    uint32_t aAddr[2], bAddr[4];
#pragma unroll
    for (int mt = 0; mt < 2; mt++)
        aAddr[mt] = smaddr(&As[0][wm0 + mt * 16 + (mat & 1) * 8 + r][(mat >> 1) * 4]);
#pragma unroll
    for (int jj = 0; jj < 4; jj++)
        bAddr[jj] = smaddr(&Bs[0][wn0 + jj * 16 + (mat >> 1) * 8 + r][(mat & 1) * 4]);

    float acc[2][8][4];
#pragma unroll
    for (int mt = 0; mt < 2; mt++)
#pragma unroll
        for (int j = 0; j < 8; j++)
#pragma unroll
            for (int v = 0; v < 4; v++) acc[mt][j][v] = 0.f;

    auto prefetch = [&](int kt, int s) {
        const uint32_t off = s * STAGE_BYTES;
        const uint32_t* a = Asrc + kt * 16;
        const uint32_t* b = Bsrc + kt * 16;
        cpasync16(dA + off, a);
        cpasync16(dA + off + 16, a + 4);
        cpasync16(dB + off, b);
        cpasync16(dB + off + 16, b + 4);
    };

    prefetch(0, 0);
    CP_COMMIT();

    const int NK = K / 16;
    for (int kt = 0; kt < NK; kt++) {
        const int s = kt & 1;
        if (kt + 1 < NK) prefetch(kt + 1, s ^ 1);
        CP_COMMIT();
        CP_WAIT1();
        __syncthreads();

        const uint32_t soff = s * STAGE_BYTES;
#pragma unroll
        for (int ks = 0; ks < 16; ks += 8) {
            uint32_t af[2][4];
            ldmx4(af[0], aAddr[0] + soff + ks * 4);
            ldmx4(af[1], aAddr[1] + soff + ks * 4);
            if (MODE == 0) {
#pragma unroll
                for (int mt = 0; mt < 2; mt++)
#pragma unroll
                    for (int v = 0; v < 4; v++) af[mt][v] = u2tf(af[mt][v]);
            }
            uint32_t bf[4][4];
#pragma unroll
            for (int jj = 0; jj < 4; jj++)
                ldmx4(bf[jj], bAddr[jj] + soff + ks * 4);
#pragma unroll
            for (int mt = 0; mt < 2; mt++)
#pragma unroll
                for (int j = 0; j < 8; j++)
                    mma8(acc[mt][j], af[mt], &bf[j >> 1][(j & 1) * 2]);
        }
        __syncthreads();
    }

#pragma unroll
    for (int mt = 0; mt < 2; mt++) {
        const int row0 = bm + wm0 + mt * 16 + g;
#pragma unroll
        for (int j = 0; j < 8; j++) {
            const int col = bn + wn0 + j * 8 + 2 * q;
            const float b0 = bias[col], b1 = bias[col + 1];
            if (MODE == 0) {
                *(uint2*)&Ctf[(size_t)row0 * N + col] =
                    make_uint2(f2tf(acc[mt][j][0] + b0), f2tf(acc[mt][j][1] + b1));
                *(uint2*)&Ctf[(size_t)(row0 + 8) * N + col] =
                    make_uint2(f2tf(acc[mt][j][2] + b0), f2tf(acc[mt][j][3] + b1));
            } else {
                *(float2*)&Cp[(size_t)row0 * N + col] =
                    make_float2(acc[mt][j][0] + b0, acc[mt][j][1] + b1);
                *(float2*)&Cp[(size_t)(row0 + 8) * N + col] =
                    make_float2(acc[mt][j][2] + b0, acc[mt][j][3] + b1);
            }
        }
    }
}

// ---------------------------------------------------------------------------
// Flash attention v2: ldmatrix fragments + cp.async double-buffered K +
// register-prefetched V (stored transposed).
// Grid: (16 q-tiles, 32 batch*head). Block: 256 threads = 8 warps; warp w
// owns q-rows w*16..+15.
// smem (words): Q[128][68] | K[2][64][68] | Vt[2][64][68] | P[128][68] | bias[2][64]
// ---------------------------------------------------------------------------
#define FSTR 68                       // 272B rows: ldmatrix conflict-free
#define KSTAGE_W (64 * FSTR)          // 4352 words per stage
#define SM_Q  0
#define SM_K  (SM_Q + 128 * FSTR)
#define SM_V  (SM_K + 2 * KSTAGE_W)
#define SM_P  (SM_V + 2 * KSTAGE_W)
#define SM_BIAS (SM_P + 128 * FSTR)
#define FLASH_SMEM_WORDS (SM_BIAS + 128)
#define FLASH_SMEM_BYTES (FLASH_SMEM_WORDS * 4)

__global__ __launch_bounds__(256) void flash_tf32(
    const float* __restrict__ attn_bias)   // [2][2048]
{
    const uint32_t* qkv = g_heap + OFF_QKV;
    uint32_t* att       = g_heap + OFF_U;

    extern __shared__ uint32_t smw[];
    uint32_t* Qs  = smw + SM_Q;
    uint32_t* Ks  = smw + SM_K;       // + s*KSTAGE_W
    uint32_t* Vts = smw + SM_V;       // + s*KSTAGE_W ; [d][key]
    uint32_t* Ps  = smw + SM_P;
    float* biass  = (float*)(smw + SM_BIAS);   // [2][64]

    const int tid  = threadIdx.x;
    const int lane = tid & 31;
    const int wid  = tid >> 5;
    const int g    = lane >> 2;
    const int q    = lane & 3;

    const int qtile = blockIdx.x;
    const int bh    = blockIdx.y;
    const int b = bh >> 4;
    const int h = bh & 15;
    const int q0 = qtile * 128;

    const int wm = wid * 16;
    const int m  = wm + g;

    // ---- ldmatrix base addresses ----
    const int mat = lane >> 3, r = lane & 7;
    const uint32_t qAddr = smaddr(&Qs[(wm + (mat & 1) * 8 + r) * FSTR + (mat >> 1) * 4]);
    const uint32_t pAddr = smaddr(&Ps[(wm + (mat & 1) * 8 + r) * FSTR + (mat >> 1) * 4]);
    uint32_t kAddr[4], vAddr[4];
#pragma unroll
    for (int jj = 0; jj < 4; jj++) {
        kAddr[jj] = smaddr(&Ks[(jj * 16 + (mat >> 1) * 8 + r) * FSTR + (mat & 1) * 4]);
        vAddr[jj] = smaddr(&Vts[(jj * 16 + (mat >> 1) * 8 + r) * FSTR + (mat & 1) * 4]);
    }
    const uint32_t KSTAGE_B = KSTAGE_W * 4;

    // ---- global pointers ----
    const uint32_t* qbase = qkv + ((size_t)(b * SEQ + q0)) * 3072 + h * HDIM;
    const uint32_t* kroot = qkv + ((size_t)(b * SEQ)) * 3072 + DMODEL + h * HDIM;
    const uint32_t* vroot = kroot + DMODEL;

    // cp.async K mapping: thread -> key=tid>>2, 64B chunk at (tid&3)*16
    const int ck_key = tid >> 2;
    const int ck_c   = (tid & 3) * 16;
    const uint32_t dK = smaddr(&Ks[ck_key * FSTR + ck_c]);

    // V register-prefetch mapping: idx=rep*256+tid -> key=idx>>4, c4=(idx&15)*4
    const int vkey = tid >> 4;            // rep adds 16 keys
    const int vc4  = (tid & 15) * 4;

    auto prefetchK = [&](int kt, int s) {
        const uint32_t* src = kroot + (size_t)(kt * 64 + ck_key) * 3072 + ck_c;
        const uint32_t d = dK + s * KSTAGE_B;
        cpasync16(d,      src);
        cpasync16(d + 16, src + 4);
        cpasync16(d + 32, src + 8);
        cpasync16(d + 48, src + 12);
    };

    // ---- prologue: Q tile, K(0) cp.async, V(0) regs ----
#pragma unroll
    for (int rep = 0; rep < 8; rep++) {
        int idx = rep * 256 + tid;
        int row = idx >> 4;
        int c4  = (idx & 15) * 4;
        *(uint4*)&Qs[row * FSTR + c4] = *(const uint4*)(qbase + (size_t)row * 3072 + c4);
    }
    prefetchK(0, 0);
    CP_COMMIT();

    uint4 vr[4];
#pragma unroll
    for (int rep = 0; rep < 4; rep++)
        vr[rep] = *(const uint4*)(vroot + (size_t)(rep * 16 + vkey) * 3072 + vc4);

    float o[8][4];
    float mr0 = -CUDART_INF_F, mr1 = -CUDART_INF_F;
    float l0 = 0.f, l1 = 0.f;
#pragma unroll
    for (int j = 0; j < 8; j++)
#pragma unroll
        for (int v = 0; v < 4; v++) o[j][v] = 0.f;

    const int NT = SEQ / 64;   // 32
    for (int kt = 0; kt < NT; kt++) {
        const int s = kt & 1;
        if (kt + 1 < NT) prefetchK(kt + 1, s ^ 1);
        CP_COMMIT();
        CP_WAIT1();

        // store prefetched V (transposed) + bias for this tile
        {
            uint32_t* Vt = Vts + s * KSTAGE_W;
#pragma unroll
            for (int rep = 0; rep < 4; rep++) {
                const int key = rep * 16 + vkey;
                Vt[(vc4 + 0) * FSTR + key] = vr[rep].x;
                Vt[(vc4 + 1) * FSTR + key] = vr[rep].y;
                Vt[(vc4 + 2) * FSTR + key] = vr[rep].z;
                Vt[(vc4 + 3) * FSTR + key] = vr[rep].w;
            }
            if (tid < 16)
                *(float4*)&biass[s * 64 + tid * 4] =
                    *(const float4*)(attn_bias + (size_t)b * SEQ + kt * 64 + tid * 4);
        }
        __syncthreads();

        // prefetch next V into regs (overlaps compute)
        if (kt + 1 < NT) {
#pragma unroll
            for (int rep = 0; rep < 4; rep++)
                vr[rep] = *(const uint4*)(vroot + (size_t)((kt + 1) * 64 + rep * 16 + vkey) * 3072 + vc4);
        }

        const uint32_t kOff = s * KSTAGE_B;

        // ---- S = Q @ K^T ----
        float sv[8][4];
#pragma unroll
        for (int j = 0; j < 8; j++)
#pragma unroll
            for (int v = 0; v < 4; v++) sv[j][v] = 0.f;

#pragma unroll
        for (int ks = 0; ks < 64; ks += 8) {
            uint32_t af[4];
            ldmx4(af, qAddr + ks * 4);
            uint32_t bf[4][4];
#pragma unroll
            for (int jj = 0; jj < 4; jj++)
                ldmx4(bf[jj], kAddr[jj] + kOff + ks * 4);
#pragma unroll
            for (int j = 0; j < 8; j++)
                mma8(sv[j], af, &bf[j >> 1][(j & 1) * 2]);
        }

        // ---- scale + bias, online softmax ----
        float mt0 = -CUDART_INF_F, mt1 = -CUDART_INF_F;
#pragma unroll
        for (int j = 0; j < 8; j++) {
            const int col = j * 8 + 2 * q;
            const float b0 = biass[s * 64 + col], b1 = biass[s * 64 + col + 1];
            sv[j][0] = fmaf(sv[j][0], 0.125f, b0);
            sv[j][1] = fmaf(sv[j][1], 0.125f, b1);
            sv[j][2] = fmaf(sv[j][2], 0.125f, b0);
            sv[j][3] = fmaf(sv[j][3], 0.125f, b1);
            mt0 = fmaxf(mt0, fmaxf(sv[j][0], sv[j][1]));
            mt1 = fmaxf(mt1, fmaxf(sv[j][2], sv[j][3]));
        }
        mt0 = fmaxf(mt0, __shfl_xor_sync(0xffffffffu, mt0, 1));
        mt0 = fmaxf(mt0, __shfl_xor_sync(0xffffffffu, mt0, 2));
        mt1 = fmaxf(mt1, __shfl_xor_sync(0xffffffffu, mt1, 1));
        mt1 = fmaxf(mt1, __shfl_xor_sync(0xffffffffu, mt1, 2));

        const float mn0 = fmaxf(mr0, mt0);
        const float mn1 = fmaxf(mr1, mt1);
        const float a0 = __expf(mr0 - mn0);
        const float a1 = __expf(mr1 - mn1);
        mr0 = mn0; mr1 = mn1;

        float rs0 = 0.f, rs1 = 0.f;
#pragma unroll
        for (int j = 0; j < 8; j++) {
            float p0 = __expf(sv[j][0] - mn0);
            float p1 = __expf(sv[j][1] - mn0);
            float p2 = __expf(sv[j][2] - mn1);
            float p3 = __expf(sv[j][3] - mn1);
            rs0 += p0 + p1;
            rs1 += p2 + p3;
            const int col = j * 8 + 2 * q;
            *(uint2*)&Ps[m * FSTR + col]       = make_uint2(f2tf(p0), f2tf(p1));
            *(uint2*)&Ps[(m + 8) * FSTR + col] = make_uint2(f2tf(p2), f2tf(p3));
        }
        rs0 += __shfl_xor_sync(0xffffffffu, rs0, 1);
        rs0 += __shfl_xor_sync(0xffffffffu, rs0, 2);
        rs1 += __shfl_xor_sync(0xffffffffu, rs1, 1);
        rs1 += __shfl_xor_sync(0xffffffffu, rs1, 2);
        l0 = l0 * a0 + rs0;
        l1 = l1 * a1 + rs1;

#pragma unroll
        for (int j = 0; j < 8; j++) {
            o[j][0] *= a0; o[j][1] *= a0;
            o[j][2] *= a1; o[j][3] *= a1;
        }
        __syncwarp();   // Ps rows are warp-private; order stores before ldmatrix

        // ---- O += P @ V ----
#pragma unroll
        for (int ks = 0; ks < 64; ks += 8) {
            uint32_t af[4];
            ldmx4(af, pAddr + ks * 4);
            uint32_t bf[4][4];
#pragma unroll
            for (int jj = 0; jj < 4; jj++)
                ldmx4(bf[jj], vAddr[jj] + kOff + ks * 4);
#pragma unroll
            for (int j = 0; j < 8; j++)
                mma8(o[j], af, &bf[j >> 1][(j & 1) * 2]);
        }
        __syncthreads();   // protect Ks/Vts stage s from next iteration's writers
    }

    // ---- epilogue: normalize, store tf32 for proj GEMM ----
    const float inv0 = 1.0f / l0;
    const float inv1 = 1.0f / l1;
    const size_t row0 = (size_t)(b * SEQ + q0 + m);
#pragma unroll
    for (int j = 0; j < 8; j++) {
        const int col = h * HDIM + j * 8 + 2 * q;
        *(uint2*)&att[row0 * DMODEL + col] =
            make_uint2(f2tf(o[j][0] * inv0), f2tf(o[j][1] * inv0));
        *(uint2*)&att[(row0 + 8) * DMODEL + col] =
            make_uint2(f2tf(o[j][2] * inv1), f2tf(o[j][3] * inv1));
    }
}

// ---------------------------------------------------------------------------
// Launch (single stream; ordering provides the aliasing safety)
// ---------------------------------------------------------------------------
extern "C" void kernel_launch(void* const* d_in, const int* in_sizes, int n_in,
                              void* d_out, int out_size)
{
    const float* x      = (const float*)d_in[0];
    const float* attnb  = (const float*)d_in[1];
    const float* w_qkv  = (const float*)d_in[2];
    const float* b_qkv  = (const float*)d_in[3];
    const float* w_proj = (const float*)d_in[4];
    const float* b_proj = (const float*)d_in[5];
    float* out = (float*)d_out;

    cudaFuncSetAttribute(flash_tf32, cudaFuncAttributeMaxDynamicSharedMemorySize,
                         FLASH_SMEM_BYTES);

    // 1) w_qkv^T (tf32) -> heap+OFF_U
    transpose_cvt<<<dim3(3 * DMODEL / 32, DMODEL / 32), dim3(32, 8)>>>(w_qkv, OFF_U, 3 * DMODEL);

    // 2) qkv = x @ w_qkv + b_qkv -> heap+OFF_QKV (tf32)
    tgemm<0><<<dim3(3 * DMODEL / 128, MROWS / 128), 256>>>(x, b_qkv, nullptr, 3 * DMODEL);

    // 3) attention: qkv -> att at heap+OFF_U (w_qkvT now dead)
    flash_tf32<<<dim3(SEQ / 128, BATCH * NHEAD), 256, FLASH_SMEM_BYTES>>>(attnb);

    // 4) w_proj^T (tf32) -> heap+OFF_WPROJ (qkv now dead)
    transpose_cvt<<<dim3(DMODEL / 32, DMODEL / 32), dim3(32, 8)>>>(w_proj, OFF_WPROJ, DMODEL);

    // 5) out = att @ w_proj + b_proj (fp32)
    tgemm<1><<<dim3(DMODEL / 128, MROWS / 128), 256>>>(nullptr, b_proj, out, DMODEL);
}

// round 7
// speedup vs baseline: 1.1055x; 1.1055x over previous
#include <cuda_runtime.h>
#include <cuda_bf16.h>
#include <math_constants.h>
#include <cstdint>

// Problem shape (fixed by the dataset)
#define BATCH 2
#define SEQ   2048
#define DMODEL 1024
#define NHEAD 16
#define HDIM  64
#define MROWS (BATCH*SEQ)          // 4096

// ---------------------------------------------------------------------------
// Single 64 MiB heap, aliased (known-passing budget):
//   [0, 12M words)   : qkv tf32 [4096][3072] ; later w_projT [1024][1024]
//   [12M, 16M words) : w_qkvT tf32 [3072][1024] ; later att tf32 [4096][1024]
// ---------------------------------------------------------------------------
#define OFF_QKV   0
#define OFF_WPROJ 0
#define OFF_U     (12u * 1024u * 1024u)
__device__ uint32_t g_heap[16u * 1024u * 1024u];

// ---------------------------------------------------------------------------
// helpers
// ---------------------------------------------------------------------------
__device__ __forceinline__ uint32_t f2tf(float x) {
    uint32_t u;
    asm("cvt.rna.tf32.f32 %0, %1;" : "=r"(u) : "f"(x));
    return u;
}
__device__ __forceinline__ uint32_t u2tf(uint32_t xb) {
    return f2tf(__uint_as_float(xb));
}
__device__ __forceinline__ uint32_t smaddr(const void* p) {
    return (uint32_t)__cvta_generic_to_shared(p);
}
__device__ __forceinline__ void ldmx4(uint32_t* r, uint32_t addr) {
    asm volatile("ldmatrix.sync.aligned.m8n8.x4.shared.b16 {%0,%1,%2,%3}, [%4];"
                 : "=r"(r[0]), "=r"(r[1]), "=r"(r[2]), "=r"(r[3]) : "r"(addr));
}
__device__ __forceinline__ void cpasync16(uint32_t dst, const void* src) {
    asm volatile("cp.async.cg.shared.global [%0], [%1], 16;" :: "r"(dst), "l"(src));
}
#define CP_COMMIT() asm volatile("cp.async.commit_group;")
#define CP_WAIT1()  asm volatile("cp.async.wait_group 1;")

// D(16x8) += A(16x8) * B(8x8); fp32 accum.
__device__ __forceinline__ void mma8(float* c, const uint32_t* a, const uint32_t* b) {
    asm volatile(
        "mma.sync.aligned.m16n8k8.row.col.f32.tf32.tf32.f32 "
        "{%0,%1,%2,%3}, {%4,%5,%6,%7}, {%8,%9}, {%0,%1,%2,%3};\n"
        : "+f"(c[0]), "+f"(c[1]), "+f"(c[2]), "+f"(c[3])
        : "r"(a[0]), "r"(a[1]), "r"(a[2]), "r"(a[3]), "r"(b[0]), "r"(b[1]));
}

// ---------------------------------------------------------------------------
// Transpose + convert: W [1024][Ncols] fp32 -> g_heap[dstOff..] [Ncols][1024] tf32
// ---------------------------------------------------------------------------
__global__ __launch_bounds__(256) void transpose_cvt(
    const float* __restrict__ W, unsigned dstOff, int Ncols)
{
    __shared__ uint32_t t[32][33];
    uint32_t* out = g_heap + dstOff;
    const int n0 = blockIdx.x * 32, k0 = blockIdx.y * 32;
    const int tx = threadIdx.x, ty = threadIdx.y;   // 32 x 8
#pragma unroll
    for (int i = 0; i < 32; i += 8)
        t[ty + i][tx] = f2tf(W[(size_t)(k0 + ty + i) * Ncols + n0 + tx]);
    __syncthreads();
#pragma unroll
    for (int i = 0; i < 32; i += 8)
        out[(size_t)(n0 + ty + i) * DMODEL + k0 + tx] = t[tx][ty + i];
}

// ---------------------------------------------------------------------------
// tf32 GEMM, double-buffered cp.async + ldmatrix (unchanged — proven).
// ---------------------------------------------------------------------------
#define TSTR 20
#define STAGE_BYTES (128 * TSTR * 4)

template<int MODE>
__global__ __launch_bounds__(256) void tgemm(
    const float* __restrict__ Ap, const float* __restrict__ bias,
    float* __restrict__ Cp, int N)
{
    const uint32_t* A = (MODE == 0) ? (const uint32_t*)Ap : g_heap + OFF_U;
    const uint32_t* B = (MODE == 0) ? g_heap + OFF_U : g_heap + OFF_WPROJ;
    uint32_t* Ctf = g_heap + OFF_QKV;
    constexpr int K = DMODEL;

    __shared__ uint32_t As[2][128][TSTR];
    __shared__ uint32_t Bs[2][128][TSTR];

    const int tid  = threadIdx.x;
    const int lane = tid & 31;
    const int wid  = tid >> 5;
    const int g    = lane >> 2;
    const int q    = lane & 3;

    const int bm = blockIdx.y * 128;
    const int bn = blockIdx.x * 128;
    const int wm0 = (wid >> 1) * 32;
    const int wn0 = (wid & 1) * 64;

    const int lrow = tid >> 1;
    const int lk   = (tid & 1) * 8;
    const uint32_t* Asrc = A + (size_t)(bm + lrow) * K + lk;
    const uint32_t* Bsrc = B + (size_t)(bn + lrow) * K + lk;
    const uint32_t dA = smaddr(&As[0][lrow][lk]);
    const uint32_t dB = smaddr(&Bs[0][lrow][lk]);

    const int mat = lane >> 3, r = lane & 7;
    uint32_t aAddr[2], bAddr[4];
#pragma unroll
    for (int mt = 0; mt < 2; mt++)
        aAddr[mt] = smaddr(&As[0][wm0 + mt * 16 + (mat & 1) * 8 + r][(mat >> 1) * 4]);
#pragma unroll
    for (int jj = 0; jj < 4; jj++)
        bAddr[jj] = smaddr(&Bs[0][wn0 + jj * 16 + (mat >> 1) * 8 + r][(mat & 1) * 4]);

    float acc[2][8][4];
#pragma unroll
    for (int mt = 0; mt < 2; mt++)
#pragma unroll
        for (int j = 0; j < 8; j++)
#pragma unroll
            for (int v = 0; v < 4; v++) acc[mt][j][v] = 0.f;

    auto prefetch = [&](int kt, int s) {
        const uint32_t off = s * STAGE_BYTES;
        const uint32_t* a = Asrc + kt * 16;
        const uint32_t* b = Bsrc + kt * 16;
        cpasync16(dA + off, a);
        cpasync16(dA + off + 16, a + 4);
        cpasync16(dB + off, b);
        cpasync16(dB + off + 16, b + 4);
    };

    prefetch(0, 0);
    CP_COMMIT();

    const int NK = K / 16;
    for (int kt = 0; kt < NK; kt++) {
        const int s = kt & 1;
        if (kt + 1 < NK) prefetch(kt + 1, s ^ 1);
        CP_COMMIT();
        CP_WAIT1();
        __syncthreads();

        const uint32_t soff = s * STAGE_BYTES;
#pragma unroll
        for (int ks = 0; ks < 16; ks += 8) {
            uint32_t af[2][4];
            ldmx4(af[0], aAddr[0] + soff + ks * 4);
            ldmx4(af[1], aAddr[1] + soff + ks * 4);
            if (MODE == 0) {
#pragma unroll
                for (int mt = 0; mt < 2; mt++)
#pragma unroll
                    for (int v = 0; v < 4; v++) af[mt][v] = u2tf(af[mt][v]);
            }
            uint32_t bf[4][4];
#pragma unroll
            for (int jj = 0; jj < 4; jj++)
                ldmx4(bf[jj], bAddr[jj] + soff + ks * 4);
#pragma unroll
            for (int mt = 0; mt < 2; mt++)
#pragma unroll
                for (int j = 0; j < 8; j++)
                    mma8(acc[mt][j], af[mt], &bf[j >> 1][(j & 1) * 2]);
        }
        __syncthreads();
    }

#pragma unroll
    for (int mt = 0; mt < 2; mt++) {
        const int row0 = bm + wm0 + mt * 16 + g;
#pragma unroll
        for (int j = 0; j < 8; j++) {
            const int col = bn + wn0 + j * 8 + 2 * q;
            const float b0 = bias[col], b1 = bias[col + 1];
            if (MODE == 0) {
                *(uint2*)&Ctf[(size_t)row0 * N + col] =
                    make_uint2(f2tf(acc[mt][j][0] + b0), f2tf(acc[mt][j][1] + b1));
                *(uint2*)&Ctf[(size_t)(row0 + 8) * N + col] =
                    make_uint2(f2tf(acc[mt][j][2] + b0), f2tf(acc[mt][j][3] + b1));
            } else {
                *(float2*)&Cp[(size_t)row0 * N + col] =
                    make_float2(acc[mt][j][0] + b0, acc[mt][j][1] + b1);
                *(float2*)&Cp[(size_t)(row0 + 8) * N + col] =
                    make_float2(acc[mt][j][2] + b0, acc[mt][j][3] + b1);
            }
        }
    }
}

// ---------------------------------------------------------------------------
// Flash attention v3: ldmatrix fragments, SINGLE-stage K/Vt smem (102 KB ->
// 2 CTAs/SM), K and V register-prefetched across tiles.
// Grid: (16 q-tiles, 32 batch*head). Block: 256 threads = 8 warps; warp w
// owns q-rows w*16..+15.
// smem (words): Q[128][68] | K[64][68] | Vt[64][68] | P[128][68] | bias[64]
// ---------------------------------------------------------------------------
#define FSTR 68                       // 272B rows: ldmatrix conflict-free
#define SM_Q  0
#define SM_K  (SM_Q + 128 * FSTR)
#define SM_V  (SM_K + 64 * FSTR)
#define SM_P  (SM_V + 64 * FSTR)
#define SM_BIAS (SM_P + 128 * FSTR)
#define FLASH_SMEM_WORDS (SM_BIAS + 64)
#define FLASH_SMEM_BYTES (FLASH_SMEM_WORDS * 4)

__global__ __launch_bounds__(256, 2) void flash_tf32(
    const float* __restrict__ attn_bias)   // [2][2048]
{
    const uint32_t* qkv = g_heap + OFF_QKV;
    uint32_t* att       = g_heap + OFF_U;

    extern __shared__ uint32_t smw[];
    uint32_t* Qs  = smw + SM_Q;
    uint32_t* Ks  = smw + SM_K;
    uint32_t* Vts = smw + SM_V;       // [d][key]
    uint32_t* Ps  = smw + SM_P;
    float* biass  = (float*)(smw + SM_BIAS);

    const int tid  = threadIdx.x;
    const int lane = tid & 31;
    const int wid  = tid >> 5;
    const int g    = lane >> 2;
    const int q    = lane & 3;

    const int qtile = blockIdx.x;
    const int bh    = blockIdx.y;
    const int b = bh >> 4;
    const int h = bh & 15;
    const int q0 = qtile * 128;

    const int wm = wid * 16;
    const int m  = wm + g;

    // ---- ldmatrix base addresses ----
    const int mat = lane >> 3, r = lane & 7;
    const uint32_t qAddr = smaddr(&Qs[(wm + (mat & 1) * 8 + r) * FSTR + (mat >> 1) * 4]);
    const uint32_t pAddr = smaddr(&Ps[(wm + (mat & 1) * 8 + r) * FSTR + (mat >> 1) * 4]);
    uint32_t kAddr[4], vAddr[4];
#pragma unroll
    for (int jj = 0; jj < 4; jj++) {
        kAddr[jj] = smaddr(&Ks[(jj * 16 + (mat >> 1) * 8 + r) * FSTR + (mat & 1) * 4]);
        vAddr[jj] = smaddr(&Vts[(jj * 16 + (mat >> 1) * 8 + r) * FSTR + (mat & 1) * 4]);
    }

    // ---- global pointers ----
    const uint32_t* qbase = qkv + ((size_t)(b * SEQ + q0)) * 3072 + h * HDIM;
    const uint32_t* kroot = qkv + ((size_t)(b * SEQ)) * 3072 + DMODEL + h * HDIM;
    const uint32_t* vroot = kroot + DMODEL;

    // K/V register-prefetch mapping: key = rep*16 + (tid>>4), c4 = (tid&15)*4
    const int pkey = tid >> 4;
    const int pc4  = (tid & 15) * 4;

    // ---- prologue: Q tile; K(0), V(0) into regs ----
#pragma unroll
    for (int rep = 0; rep < 8; rep++) {
        int idx = rep * 256 + tid;
        int row = idx >> 4;
        int c4  = (idx & 15) * 4;
        *(uint4*)&Qs[row * FSTR + c4] = *(const uint4*)(qbase + (size_t)row * 3072 + c4);
    }
    uint4 kr[4], vr[4];
#pragma unroll
    for (int rep = 0; rep < 4; rep++) {
        kr[rep] = *(const uint4*)(kroot + (size_t)(rep * 16 + pkey) * 3072 + pc4);
        vr[rep] = *(const uint4*)(vroot + (size_t)(rep * 16 + pkey) * 3072 + pc4);
    }
    float bias_r = attn_bias[(size_t)b * SEQ + (tid & 63)];   // tile 0 bias (tid<64 used)

    float o[8][4];
    float mr0 = -CUDART_INF_F, mr1 = -CUDART_INF_F;
    float l0 = 0.f, l1 = 0.f;
#pragma unroll
    for (int j = 0; j < 8; j++)
#pragma unroll
        for (int v = 0; v < 4; v++) o[j][v] = 0.f;

    const int NT = SEQ / 64;   // 32
    for (int kt = 0; kt < NT; kt++) {
        // ---- store prefetched K (rows) / V (transposed) / bias ----
#pragma unroll
        for (int rep = 0; rep < 4; rep++) {
            const int key = rep * 16 + pkey;
            *(uint4*)&Ks[key * FSTR + pc4] = kr[rep];
            Vts[(pc4 + 0) * FSTR + key] = vr[rep].x;
            Vts[(pc4 + 1) * FSTR + key] = vr[rep].y;
            Vts[(pc4 + 2) * FSTR + key] = vr[rep].z;
            Vts[(pc4 + 3) * FSTR + key] = vr[rep].w;
        }
        if (tid < 64) biass[tid] = bias_r;
        __syncthreads();

        // ---- issue next tile's K/V/bias loads (fly during compute) ----
        if (kt + 1 < NT) {
#pragma unroll
            for (int rep = 0; rep < 4; rep++) {
                kr[rep] = *(const uint4*)(kroot + (size_t)((kt + 1) * 64 + rep * 16 + pkey) * 3072 + pc4);
                vr[rep] = *(const uint4*)(vroot + (size_t)((kt + 1) * 64 + rep * 16 + pkey) * 3072 + pc4);
            }
            bias_r = attn_bias[(size_t)b * SEQ + (kt + 1) * 64 + (tid & 63)];
        }

        // ---- S = Q @ K^T ----
        float sv[8][4];
#pragma unroll
        for (int j = 0; j < 8; j++)
#pragma unroll
            for (int v = 0; v < 4; v++) sv[j][v] = 0.f;

#pragma unroll
        for (int ks = 0; ks < 64; ks += 8) {
            uint32_t af[4];
            ldmx4(af, qAddr + ks * 4);
            uint32_t bf[4][4];
#pragma unroll
            for (int jj = 0; jj < 4; jj++)
                ldmx4(bf[jj], kAddr[jj] + ks * 4);
#pragma unroll
            for (int j = 0; j < 8; j++)
                mma8(sv[j], af, &bf[j >> 1][(j & 1) * 2]);
        }

        // ---- scale + bias, online softmax ----
        float mt0 = -CUDART_INF_F, mt1 = -CUDART_INF_F;
#pragma unroll
        for (int j = 0; j < 8; j++) {
            const int col = j * 8 + 2 * q;
            const float b0 = biass[col], b1 = biass[col + 1];
            sv[j][0] = fmaf(sv[j][0], 0.125f, b0);
            sv[j][1] = fmaf(sv[j][1], 0.125f, b1);
            sv[j][2] = fmaf(sv[j][2], 0.125f, b0);
            sv[j][3] = fmaf(sv[j][3], 0.125f, b1);
            mt0 = fmaxf(mt0, fmaxf(sv[j][0], sv[j][1]));
            mt1 = fmaxf(mt1, fmaxf(sv[j][2], sv[j][3]));
        }
        mt0 = fmaxf(mt0, __shfl_xor_sync(0xffffffffu, mt0, 1));
        mt0 = fmaxf(mt0, __shfl_xor_sync(0xffffffffu, mt0, 2));
        mt1 = fmaxf(mt1, __shfl_xor_sync(0xffffffffu, mt1, 1));
        mt1 = fmaxf(mt1, __shfl_xor_sync(0xffffffffu, mt1, 2));

        const float mn0 = fmaxf(mr0, mt0);
        const float mn1 = fmaxf(mr1, mt1);
        const float a0 = __expf(mr0 - mn0);
        const float a1 = __expf(mr1 - mn1);
        mr0 = mn0; mr1 = mn1;

        float rs0 = 0.f, rs1 = 0.f;
#pragma unroll
        for (int j = 0; j < 8; j++) {
            float p0 = __expf(sv[j][0] - mn0);
            float p1 = __expf(sv[j][1] - mn0);
            float p2 = __expf(sv[j][2] - mn1);
            float p3 = __expf(sv[j][3] - mn1);
            rs0 += p0 + p1;
            rs1 += p2 + p3;
            const int col = j * 8 + 2 * q;
            *(uint2*)&Ps[m * FSTR + col]       = make_uint2(f2tf(p0), f2tf(p1));
            *(uint2*)&Ps[(m + 8) * FSTR + col] = make_uint2(f2tf(p2), f2tf(p3));
        }
        rs0 += __shfl_xor_sync(0xffffffffu, rs0, 1);
        rs0 += __shfl_xor_sync(0xffffffffu, rs0, 2);
        rs1 += __shfl_xor_sync(0xffffffffu, rs1, 1);
        rs1 += __shfl_xor_sync(0xffffffffu, rs1, 2);
        l0 = l0 * a0 + rs0;
        l1 = l1 * a1 + rs1;

#pragma unroll
        for (int j = 0; j < 8; j++) {
            o[j][0] *= a0; o[j][1] *= a0;
            o[j][2] *= a1; o[j][3] *= a1;
        }
        __syncwarp();   // Ps rows are warp-private; order stores before ldmatrix

        // ---- O += P @ V ----
#pragma unroll
        for (int ks = 0; ks < 64; ks += 8) {
            uint32_t af[4];
            ldmx4(af, pAddr + ks * 4);
            uint32_t bf[4][4];
#pragma unroll
            for (int jj = 0; jj < 4; jj++)
                ldmx4(bf[jj], vAddr[jj] + ks * 4);
#pragma unroll
            for (int j = 0; j < 8; j++)
                mma8(o[j], af, &bf[j >> 1][(j & 1) * 2]);
        }
        __syncthreads();   // all readers done before next tile's stores
    }

    // ---- epilogue: normalize, store tf32 for proj GEMM ----
    const float inv0 = 1.0f / l0;
    const float inv1 = 1.0f / l1;
    const size_t row0 = (size_t)(b * SEQ + q0 + m);
#pragma unroll
    for (int j = 0; j < 8; j++) {
        const int col = h * HDIM + j * 8 + 2 * q;
        *(uint2*)&att[row0 * DMODEL + col] =
            make_uint2(f2tf(o[j][0] * inv0), f2tf(o[j][1] * inv0));
        *(uint2*)&att[(row0 + 8) * DMODEL + col] =
            make_uint2(f2tf(o[j][2] * inv1), f2tf(o[j][3] * inv1));
    }
}

// ---------------------------------------------------------------------------
// Launch (single stream; ordering provides the aliasing safety)
// ---------------------------------------------------------------------------
extern "C" void kernel_launch(void* const* d_in, const int* in_sizes, int n_in,
                              void* d_out, int out_size)
{
    const float* x      = (const float*)d_in[0];
    const float* attnb  = (const float*)d_in[1];
    const float* w_qkv  = (const float*)d_in[2];
    const float* b_qkv  = (const float*)d_in[3];
    const float* w_proj = (const float*)d_in[4];
    const float* b_proj = (const float*)d_in[5];
    float* out = (float*)d_out;

    cudaFuncSetAttribute(flash_tf32, cudaFuncAttributeMaxDynamicSharedMemorySize,
                         FLASH_SMEM_BYTES);

    // 1) w_qkv^T (tf32) -> heap+OFF_U
    transpose_cvt<<<dim3(3 * DMODEL / 32, DMODEL / 32), dim3(32, 8)>>>(w_qkv, OFF_U, 3 * DMODEL);

    // 2) qkv = x @ w_qkv + b_qkv -> heap+OFF_QKV (tf32)
    tgemm<0><<<dim3(3 * DMODEL / 128, MROWS / 128), 256>>>(x, b_qkv, nullptr, 3 * DMODEL);

    // 3) attention: qkv -> att at heap+OFF_U (w_qkvT now dead)
    flash_tf32<<<dim3(SEQ / 128, BATCH * NHEAD), 256, FLASH_SMEM_BYTES>>>(attnb);

    // 4) w_proj^T (tf32) -> heap+OFF_WPROJ (qkv now dead)
    transpose_cvt<<<dim3(DMODEL / 32, DMODEL / 32), dim3(32, 8)>>>(w_proj, OFF_WPROJ, DMODEL);

    // 5) out = att @ w_proj + b_proj (fp32)
    tgemm<1><<<dim3(DMODEL / 128, MROWS / 128), 256>>>(nullptr, b_proj, out, DMODEL);
}

// round 9
// speedup vs baseline: 1.1125x; 1.0063x over previous
#include <cuda_runtime.h>
#include <cuda_bf16.h>
#include <math_constants.h>
#include <cstdint>

// Problem shape (fixed by the dataset)
#define BATCH 2
#define SEQ   2048
#define DMODEL 1024
#define NHEAD 16
#define HDIM  64
#define MROWS (BATCH*SEQ)          // 4096

// ---------------------------------------------------------------------------
// Single 64 MiB heap, aliased (known-passing budget):
//   [0, 12M words)   : qkv tf32 [4096][3072] ; later w_projT [1024][1024]
//   [12M, 16M words) : w_qkvT tf32 [3072][1024] ; later att tf32 [4096][1024]
// ---------------------------------------------------------------------------
#define OFF_QKV   0
#define OFF_WPROJ 0
#define OFF_U     (12u * 1024u * 1024u)
__device__ uint32_t g_heap[16u * 1024u * 1024u];

// ---------------------------------------------------------------------------
// helpers
// ---------------------------------------------------------------------------
__device__ __forceinline__ uint32_t f2tf(float x) {
    uint32_t u;
    asm("cvt.rna.tf32.f32 %0, %1;" : "=r"(u) : "f"(x));
    return u;
}
__device__ __forceinline__ uint32_t u2tf(uint32_t xb) {
    return f2tf(__uint_as_float(xb));
}
__device__ __forceinline__ uint32_t smaddr(const void* p) {
    return (uint32_t)__cvta_generic_to_shared(p);
}
__device__ __forceinline__ void ldmx4(uint32_t* r, uint32_t addr) {
    asm volatile("ldmatrix.sync.aligned.m8n8.x4.shared.b16 {%0,%1,%2,%3}, [%4];"
                 : "=r"(r[0]), "=r"(r[1]), "=r"(r[2]), "=r"(r[3]) : "r"(addr));
}
__device__ __forceinline__ void cpasync16(uint32_t dst, const void* src) {
    asm volatile("cp.async.cg.shared.global [%0], [%1], 16;" :: "r"(dst), "l"(src));
}
#define CP_COMMIT() asm volatile("cp.async.commit_group;")
#define CP_WAIT1()  asm volatile("cp.async.wait_group 1;")
#define CP_WAIT0()  asm volatile("cp.async.wait_group 0;")

// D(16x8) += A(16x8) * B(8x8); fp32 accum.
__device__ __forceinline__ void mma8(float* c, const uint32_t* a, const uint32_t* b) {
    asm volatile(
        "mma.sync.aligned.m16n8k8.row.col.f32.tf32.tf32.f32 "
        "{%0,%1,%2,%3}, {%4,%5,%6,%7}, {%8,%9}, {%0,%1,%2,%3};\n"
        : "+f"(c[0]), "+f"(c[1]), "+f"(c[2]), "+f"(c[3])
        : "r"(a[0]), "r"(a[1]), "r"(a[2]), "r"(a[3]), "r"(b[0]), "r"(b[1]));
}

// no-op spacer so ncu's "-s 5 -c 1" capture lands on flash_tf32
__global__ void spacer_k() {}

// ---------------------------------------------------------------------------
// Transpose + convert: W [1024][Ncols] fp32 -> g_heap[dstOff..] [Ncols][1024] tf32
// ---------------------------------------------------------------------------
__global__ __launch_bounds__(256) void transpose_cvt(
    const float* __restrict__ W, unsigned dstOff, int Ncols)
{
    __shared__ uint32_t t[32][33];
    uint32_t* out = g_heap + dstOff;
    const int n0 = blockIdx.x * 32, k0 = blockIdx.y * 32;
    const int tx = threadIdx.x, ty = threadIdx.y;   // 32 x 8
#pragma unroll
    for (int i = 0; i < 32; i += 8)
        t[ty + i][tx] = f2tf(W[(size_t)(k0 + ty + i) * Ncols + n0 + tx]);
    __syncthreads();
#pragma unroll
    for (int i = 0; i < 32; i += 8)
        out[(size_t)(n0 + ty + i) * DMODEL + k0 + tx] = t[tx][ty + i];
}

// ---------------------------------------------------------------------------
// tf32 GEMM, double-buffered cp.async + ldmatrix (unchanged — proven).
// ---------------------------------------------------------------------------
#define TSTR 20
#define STAGE_BYTES (128 * TSTR * 4)

template<int MODE>
__global__ __launch_bounds__(256) void tgemm(
    const float* __restrict__ Ap, const float* __restrict__ bias,
    float* __restrict__ Cp, int N)
{
    const uint32_t* A = (MODE == 0) ? (const uint32_t*)Ap : g_heap + OFF_U;
    const uint32_t* B = (MODE == 0) ? g_heap + OFF_U : g_heap + OFF_WPROJ;
    uint32_t* Ctf = g_heap + OFF_QKV;
    constexpr int K = DMODEL;

    __shared__ uint32_t As[2][128][TSTR];
    __shared__ uint32_t Bs[2][128][TSTR];

    const int tid  = threadIdx.x;
    const int lane = tid & 31;
    const int wid  = tid >> 5;
    const int g    = lane >> 2;
    const int q    = lane & 3;

    const int bm = blockIdx.y * 128;
    const int bn = blockIdx.x * 128;
    const int wm0 = (wid >> 1) * 32;
    const int wn0 = (wid & 1) * 64;

    const int lrow = tid >> 1;
    const int lk   = (tid & 1) * 8;
    const uint32_t* Asrc = A + (size_t)(bm + lrow) * K + lk;
    const uint32_t* Bsrc = B + (size_t)(bn + lrow) * K + lk;
    const uint32_t dA = smaddr(&As[0][lrow][lk]);
    const uint32_t dB = smaddr(&Bs[0][lrow][lk]);

    const int mat = lane >> 3, r = lane & 7;
    uint32_t aAddr[2], bAddr[4];
#pragma unroll
    for (int mt = 0; mt < 2; mt++)
        aAddr[mt] = smaddr(&As[0][wm0 + mt * 16 + (mat & 1) * 8 + r][(mat >> 1) * 4]);
#pragma unroll
    for (int jj = 0; jj < 4; jj++)
        bAddr[jj] = smaddr(&Bs[0][wn0 + jj * 16 + (mat >> 1) * 8 + r][(mat & 1) * 4]);

    float acc[2][8][4];
#pragma unroll
    for (int mt = 0; mt < 2; mt++)
#pragma unroll
        for (int j = 0; j < 8; j++)
#pragma unroll
            for (int v = 0; v < 4; v++) acc[mt][j][v] = 0.f;

    auto prefetch = [&](int kt, int s) {
        const uint32_t off = s * STAGE_BYTES;
        const uint32_t* a = Asrc + kt * 16;
        const uint32_t* b = Bsrc + kt * 16;
        cpasync16(dA + off, a);
        cpasync16(dA + off + 16, a + 4);
        cpasync16(dB + off, b);
        cpasync16(dB + off + 16, b + 4);
    };

    prefetch(0, 0);
    CP_COMMIT();

    const int NK = K / 16;
    for (int kt = 0; kt < NK; kt++) {
        const int s = kt & 1;
        if (kt + 1 < NK) prefetch(kt + 1, s ^ 1);
        CP_COMMIT();
        CP_WAIT1();
        __syncthreads();

        const uint32_t soff = s * STAGE_BYTES;
#pragma unroll
        for (int ks = 0; ks < 16; ks += 8) {
            uint32_t af[2][4];
            ldmx4(af[0], aAddr[0] + soff + ks * 4);
            ldmx4(af[1], aAddr[1] + soff + ks * 4);
            if (MODE == 0) {
#pragma unroll
                for (int mt = 0; mt < 2; mt++)
#pragma unroll
                    for (int v = 0; v < 4; v++) af[mt][v] = u2tf(af[mt][v]);
            }
            uint32_t bf[4][4];
#pragma unroll
            for (int jj = 0; jj < 4; jj++)
                ldmx4(bf[jj], bAddr[jj] + soff + ks * 4);
#pragma unroll
            for (int mt = 0; mt < 2; mt++)
#pragma unroll
                for (int j = 0; j < 8; j++)
                    mma8(acc[mt][j], af[mt], &bf[j >> 1][(j & 1) * 2]);
        }
        __syncthreads();
    }

#pragma unroll
    for (int mt = 0; mt < 2; mt++) {
        const int row0 = bm + wm0 + mt * 16 + g;
#pragma unroll
        for (int j = 0; j < 8; j++) {
            const int col = bn + wn0 + j * 8 + 2 * q;
            const float b0 = bias[col], b1 = bias[col + 1];
            if (MODE == 0) {
                *(uint2*)&Ctf[(size_t)row0 * N + col] =
                    make_uint2(f2tf(acc[mt][j][0] + b0), f2tf(acc[mt][j][1] + b1));
                *(uint2*)&Ctf[(size_t)(row0 + 8) * N + col] =
                    make_uint2(f2tf(acc[mt][j][2] + b0), f2tf(acc[mt][j][3] + b1));
            } else {
                *(float2*)&Cp[(size_t)row0 * N + col] =
                    make_float2(acc[mt][j][0] + b0, acc[mt][j][1] + b1);
                *(float2*)&Cp[(size_t)(row0 + 8) * N + col] =
                    make_float2(acc[mt][j][2] + b0, acc[mt][j][3] + b1);
            }
        }
    }
}

// ---------------------------------------------------------------------------
// Flash attention v4: single-stage smem (103 KB -> 2 CTA/SM), cp.async K/V,
// ldmatrix Q/K/P fragments, scalar V fragments (no b32 trans ldmatrix).
// Grid: (16 q-tiles, 32 batch*head). Block: 256 threads = 8 warps; warp w
// owns q-rows w*16..+15.
// smem (words): Q[128][68] | K[64][68] | V[64][72] | P[128][68] | bias[64]
// ---------------------------------------------------------------------------
#define FSTR 68
#define VSTR 72
#define SM_Q  0
#define SM_K  (SM_Q + 128 * FSTR)
#define SM_V  (SM_K + 64 * FSTR)
#define SM_P  (SM_V + 64 * VSTR)
#define SM_BIAS (SM_P + 128 * FSTR)
#define FLASH_SMEM_WORDS (SM_BIAS + 64)
#define FLASH_SMEM_BYTES (FLASH_SMEM_WORDS * 4)

__global__ __launch_bounds__(256, 2) void flash_tf32(
    const float* __restrict__ attn_bias)   // [2][2048]
{
    const uint32_t* qkv = g_heap + OFF_QKV;
    uint32_t* att       = g_heap + OFF_U;

    extern __shared__ uint32_t smw[];
    uint32_t* Qs = smw + SM_Q;
    uint32_t* Ks = smw + SM_K;     // row-major [key][d]
    uint32_t* Vs = smw + SM_V;     // row-major [key][d]
    uint32_t* Ps = smw + SM_P;
    float* biass = (float*)(smw + SM_BIAS);

    const int tid  = threadIdx.x;
    const int lane = tid & 31;
    const int wid  = tid >> 5;
    const int g    = lane >> 2;
    const int q    = lane & 3;

    const int qtile = blockIdx.x;
    const int bh    = blockIdx.y;
    const int b = bh >> 4;
    const int h = bh & 15;
    const int q0 = qtile * 128;

    const int wm = wid * 16;
    const int m  = wm + g;

    // ---- ldmatrix base addresses (R7-proven mapping) ----
    const int mat = lane >> 3, r = lane & 7;
    const uint32_t qAddr = smaddr(&Qs[(wm + (mat & 1) * 8 + r) * FSTR + (mat >> 1) * 4]);
    const uint32_t pAddr = smaddr(&Ps[(wm + (mat & 1) * 8 + r) * FSTR + (mat >> 1) * 4]);
    uint32_t kAddr[4];
#pragma unroll
    for (int jj = 0; jj < 4; jj++)
        kAddr[jj] = smaddr(&Ks[(jj * 16 + (mat >> 1) * 8 + r) * FSTR + (mat & 1) * 4]);

    // ---- global pointers ----
    const uint32_t* qbase = qkv + ((size_t)(b * SEQ + q0)) * 3072 + h * HDIM;
    const uint32_t* kroot = qkv + ((size_t)(b * SEQ)) * 3072 + DMODEL + h * HDIM;
    const uint32_t* vroot = kroot + DMODEL;

    // cp.async K/V mapping: key = tid>>2, 16-word chunk at (tid&3)*16
    const int ck  = tid >> 2;
    const int cc  = (tid & 3) * 16;
    const uint32_t dK = smaddr(&Ks[ck * FSTR + cc]);
    const uint32_t dV = smaddr(&Vs[ck * VSTR + cc]);

    // ---- prologue: Q tile (plain loads; covered by first loop sync) ----
#pragma unroll
    for (int rep = 0; rep < 8; rep++) {
        int idx = rep * 256 + tid;
        int row = idx >> 4;
        int c4  = (idx & 15) * 4;
        *(uint4*)&Qs[row * FSTR + c4] = *(const uint4*)(qbase + (size_t)row * 3072 + c4);
    }

    float o[8][4];
    float mr0 = -CUDART_INF_F, mr1 = -CUDART_INF_F;
    float l0 = 0.f, l1 = 0.f;
#pragma unroll
    for (int j = 0; j < 8; j++)
#pragma unroll
        for (int v = 0; v < 4; v++) o[j][v] = 0.f;

    const int NT = SEQ / 64;   // 32
    for (int kt = 0; kt < NT; kt++) {
        __syncthreads();   // prior readers done (kt=0: Q stores visible)

        // ---- K/V/bias -> smem via cp.async ----
        {
            const uint32_t* ks = kroot + (size_t)(kt * 64 + ck) * 3072 + cc;
            const uint32_t* vs = vroot + (size_t)(kt * 64 + ck) * 3072 + cc;
            cpasync16(dK,      ks);
            cpasync16(dK + 16, ks + 4);
            cpasync16(dK + 32, ks + 8);
            cpasync16(dK + 48, ks + 12);
            cpasync16(dV,      vs);
            cpasync16(dV + 16, vs + 4);
            cpasync16(dV + 32, vs + 8);
            cpasync16(dV + 48, vs + 12);
            if (tid < 16)
                cpasync16(smaddr(&biass[tid * 4]),
                          attn_bias + (size_t)b * SEQ + kt * 64 + tid * 4);
            CP_COMMIT();
            CP_WAIT0();
        }
        __syncthreads();

        // ---- S = Q @ K^T (ldmatrix) ----
        float sv[8][4];
#pragma unroll
        for (int j = 0; j < 8; j++)
#pragma unroll
            for (int v = 0; v < 4; v++) sv[j][v] = 0.f;

#pragma unroll
        for (int ks = 0; ks < 64; ks += 8) {
            uint32_t af[4];
            ldmx4(af, qAddr + ks * 4);
            uint32_t bf[4][4];
#pragma unroll
            for (int jj = 0; jj < 4; jj++)
                ldmx4(bf[jj], kAddr[jj] + ks * 4);
#pragma unroll
            for (int j = 0; j < 8; j++)
                mma8(sv[j], af, &bf[j >> 1][(j & 1) * 2]);
        }

        // ---- scale + bias, online softmax ----
        float mt0 = -CUDART_INF_F, mt1 = -CUDART_INF_F;
#pragma unroll
        for (int j = 0; j < 8; j++) {
            const int col = j * 8 + 2 * q;
            const float b0 = biass[col], b1 = biass[col + 1];
            sv[j][0] = fmaf(sv[j][0], 0.125f, b0);
            sv[j][1] = fmaf(sv[j][1], 0.125f, b1);
            sv[j][2] = fmaf(sv[j][2], 0.125f, b0);
            sv[j][3] = fmaf(sv[j][3], 0.125f, b1);
            mt0 = fmaxf(mt0, fmaxf(sv[j][0], sv[j][1]));
            mt1 = fmaxf(mt1, fmaxf(sv[j][2], sv[j][3]));
        }
        mt0 = fmaxf(mt0, __shfl_xor_sync(0xffffffffu, mt0, 1));
        mt0 = fmaxf(mt0, __shfl_xor_sync(0xffffffffu, mt0, 2));
        mt1 = fmaxf(mt1, __shfl_xor_sync(0xffffffffu, mt1, 1));
        mt1 = fmaxf(mt1, __shfl_xor_sync(0xffffffffu, mt1, 2));

        const float mn0 = fmaxf(mr0, mt0);
        const float mn1 = fmaxf(mr1, mt1);
        const float a0 = __expf(mr0 - mn0);
        const float a1 = __expf(mr1 - mn1);
        mr0 = mn0; mr1 = mn1;

        float rs0 = 0.f, rs1 = 0.f;
#pragma unroll
        for (int j = 0; j < 8; j++) {
            float p0 = __expf(sv[j][0] - mn0);
            float p1 = __expf(sv[j][1] - mn0);
            float p2 = __expf(sv[j][2] - mn1);
            float p3 = __expf(sv[j][3] - mn1);
            rs0 += p0 + p1;
            rs1 += p2 + p3;
            const int col = j * 8 + 2 * q;
            *(uint2*)&Ps[m * FSTR + col]       = make_uint2(f2tf(p0), f2tf(p1));
            *(uint2*)&Ps[(m + 8) * FSTR + col] = make_uint2(f2tf(p2), f2tf(p3));
        }
        rs0 += __shfl_xor_sync(0xffffffffu, rs0, 1);
        rs0 += __shfl_xor_sync(0xffffffffu, rs0, 2);
        rs1 += __shfl_xor_sync(0xffffffffu, rs1, 1);
        rs1 += __shfl_xor_sync(0xffffffffu, rs1, 2);
        l0 = l0 * a0 + rs0;
        l1 = l1 * a1 + rs1;

#pragma unroll
        for (int j = 0; j < 8; j++) {
            o[j][0] *= a0; o[j][1] *= a0;
            o[j][2] *= a1; o[j][3] *= a1;
        }
        __syncwarp();   // Ps rows are warp-private; order stores before ldmatrix

        // ---- O += P @ V (ldmatrix P, scalar V) ----
#pragma unroll
        for (int ks = 0; ks < 64; ks += 8) {
            uint32_t af[4];
            ldmx4(af, pAddr + ks * 4);
#pragma unroll
            for (int j = 0; j < 8; j++) {
                uint32_t bv[2];
                bv[0] = Vs[(ks + q) * VSTR + j * 8 + g];
                bv[1] = Vs[(ks + q + 4) * VSTR + j * 8 + g];
                mma8(o[j], af, bv);
            }
        }
    }

    // ---- epilogue: normalize, store tf32 for proj GEMM ----
    const float inv0 = 1.0f / l0;
    const float inv1 = 1.0f / l1;
    const size_t row0 = (size_t)(b * SEQ + q0 + m);
#pragma unroll
    for (int j = 0; j < 8; j++) {
        const int col = h * HDIM + j * 8 + 2 * q;
        *(uint2*)&att[row0 * DMODEL + col] =
            make_uint2(f2tf(o[j][0] * inv0), f2tf(o[j][1] * inv0));
        *(uint2*)&att[(row0 + 8) * DMODEL + col] =
            make_uint2(f2tf(o[j][2] * inv1), f2tf(o[j][3] * inv1));
    }
}

// ---------------------------------------------------------------------------
// Launch (single stream; ordering provides the aliasing safety).
// 3 spacer launches place flash_tf32 at global launch index 5 for ncu capture.
// ---------------------------------------------------------------------------
extern "C" void kernel_launch(void* const* d_in, const int* in_sizes, int n_in,
                              void* d_out, int out_size)
{
    const float* x      = (const float*)d_in[0];
    const float* attnb  = (const float*)d_in[1];
    const float* w_qkv  = (const float*)d_in[2];
    const float* b_qkv  = (const float*)d_in[3];
    const float* w_proj = (const float*)d_in[4];
    const float* b_proj = (const float*)d_in[5];
    float* out = (float*)d_out;

    cudaFuncSetAttribute(flash_tf32, cudaFuncAttributeMaxDynamicSharedMemorySize,
                         FLASH_SMEM_BYTES);

    // idx0) w_qkv^T (tf32) -> heap+OFF_U
    transpose_cvt<<<dim3(3 * DMODEL / 32, DMODEL / 32), dim3(32, 8)>>>(w_qkv, OFF_U, 3 * DMODEL);

    // idx1) qkv = x @ w_qkv + b_qkv -> heap+OFF_QKV (tf32)
    tgemm<0><<<dim3(3 * DMODEL / 128, MROWS / 128), 256>>>(x, b_qkv, nullptr, 3 * DMODEL);

    // idx2-4) spacers (align flash to capture index 5)
    spacer_k<<<1, 32>>>();
    spacer_k<<<1, 32>>>();
    spacer_k<<<1, 32>>>();

    // idx5) attention: qkv -> att at heap+OFF_U (w_qkvT now dead)
    flash_tf32<<<dim3(SEQ / 128, BATCH * NHEAD), 256, FLASH_SMEM_BYTES>>>(attnb);

    // idx6) w_proj^T (tf32) -> heap+OFF_WPROJ (qkv now dead)
    transpose_cvt<<<dim3(DMODEL / 32, DMODEL / 32), dim3(32, 8)>>>(w_proj, OFF_WPROJ, DMODEL);

    // idx7) out = att @ w_proj + b_proj (fp32)
    tgemm<1><<<dim3(DMODEL / 128, MROWS / 128), 256>>>(nullptr, b_proj, out, DMODEL);
}